// round 7
// baseline (speedup 1.0000x reference)
#include <cuda_runtime.h>
#include <cstdint>

// Problem constants
#define TT     25
#define FF     14
#define HH     24
#define KK     38     // FF + HH fused weight row
#define NSTEPS 13     // fwd needs t=0..12, bwd needs t=24..12
#define BTOT   65536
#define BLK    64
#define NCLS   4

typedef unsigned long long u64;

// ---- packed f32x2 helpers (Blackwell) ----
__device__ __forceinline__ u64 pack2(float lo, float hi) {
    u64 r; asm("mov.b64 %0, {%1, %2};" : "=l"(r) : "f"(lo), "f"(hi)); return r;
}
__device__ __forceinline__ u64 dup2(float v) {
    u64 r; asm("mov.b64 %0, {%1, %1};" : "=l"(r) : "f"(v)); return r;
}
__device__ __forceinline__ void unpack2(u64 v, float& lo, float& hi) {
    asm("mov.b64 {%0, %1}, %2;" : "=f"(lo), "=f"(hi) : "l"(v));
}
__device__ __forceinline__ void ffma2(u64& d, u64 a, u64 b) {
    asm("fma.rn.f32x2 %0, %1, %2, %0;" : "+l"(d) : "l"(a), "l"(b));
}

// ---- fast, accurate activations ----
__device__ __forceinline__ float ex2f_(float x) {
    float y; asm("ex2.approx.f32 %0, %1;" : "=f"(y) : "f"(x)); return y;
}
__device__ __forceinline__ float rcpf_(float x) {
    float y; asm("rcp.approx.f32 %0, %1;" : "=f"(y) : "f"(x)); return y;
}
__device__ __forceinline__ float sigf_(float x) {
    return rcpf_(1.0f + ex2f_(-1.4426950408889634f * x));
}
__device__ __forceinline__ float tanhf_(float x) {
    x = fminf(fmaxf(x, -30.0f), 30.0f);
    float a = ex2f_(2.8853900817779268f * x);
    return (a - 1.0f) * rcpf_(a + 1.0f);
}

// ---- packed parameter blob: device scratch -> constant ----
struct CPack {
    ulonglong2 w[2][HH * KK];   // [dir][j*KK+k] = {(wi,wf),(wg,wo)}  29184 B
    u64 bif[2][HH];             // fused biases, gate-paired            384 B
    u64 bgo[2][HH];             //                                      384 B
    float hw[2][NCLS * HH];     // head_w slice per direction           768 B
};
__device__   CPack g_pk;
__constant__ CPack c_pk;

__global__ __launch_bounds__(256)
void prep_pack_kernel(const float* __restrict__ wih_f, const float* __restrict__ whh_f,
                      const float* __restrict__ bih_f, const float* __restrict__ bhh_f,
                      const float* __restrict__ wih_b, const float* __restrict__ whh_b,
                      const float* __restrict__ bih_b, const float* __restrict__ bhh_b,
                      const float* __restrict__ head_w)
{
    for (int d = 0; d < 2; ++d) {
        const float* wih = d ? wih_b : wih_f;
        const float* whh = d ? whh_b : whh_f;
        const float* bih = d ? bih_b : bih_f;
        const float* bhh = d ? bhh_b : bhh_f;
        for (int i = threadIdx.x; i < HH * KK; i += 256) {
            int j = i / KK, k = i % KK;
            float wi, wf, wg, wo;
            if (k < FF) {
                wi = wih[j * FF + k];
                wf = wih[(j + HH) * FF + k];
                wg = wih[(j + 2 * HH) * FF + k];
                wo = wih[(j + 3 * HH) * FF + k];
            } else {
                int kk = k - FF;
                wi = whh[j * HH + kk];
                wf = whh[(j + HH) * HH + kk];
                wg = whh[(j + 2 * HH) * HH + kk];
                wo = whh[(j + 3 * HH) * HH + kk];
            }
            ulonglong2 w; w.x = pack2(wi, wf); w.y = pack2(wg, wo);
            g_pk.w[d][i] = w;
        }
        if (threadIdx.x < HH) {
            int j = threadIdx.x;
            g_pk.bif[d][j] = pack2(bih[j] + bhh[j],                   bih[j + HH] + bhh[j + HH]);
            g_pk.bgo[d][j] = pack2(bih[j + 2 * HH] + bhh[j + 2 * HH], bih[j + 3 * HH] + bhh[j + 3 * HH]);
        }
        if (threadIdx.x < NCLS * HH) {
            int m = threadIdx.x / HH, j = threadIdx.x % HH;
            g_pk.hw[d][m * HH + j] = head_w[m * (2 * HH) + d * HH + j];
        }
    }
}

__global__ __launch_bounds__(256)
void init_out_kernel(const float* __restrict__ head_b, float* __restrict__ out)
{
    const int b = blockIdx.x * blockDim.x + threadIdx.x;
    ((float4*)out)[b] = make_float4(head_b[0], head_b[1], head_b[2], head_b[3]);
}

__global__ __launch_bounds__(BLK, 7)
void lstm_kernel(const float* __restrict__ x, float* __restrict__ out)
{
    // Only per-thread state lives in smem now (weights come from constant memory).
    __shared__ float s_c [2 * BLK * 25];    // 12800 B  (stride 25: conflict-free)
    __shared__ float s_hn[2 * BLK * 25];    // 12800 B

    const int dir = blockIdx.x & 1;

    // Two batch elements per thread
    const int b0 = (blockIdx.x >> 1) * (2 * BLK) + threadIdx.x;
    const int b1 = b0 + BLK;

    float h0[HH], h1[HH];
    float* c0 = &s_c [threadIdx.x * 25];
    float* c1 = &s_c [(BLK + threadIdx.x) * 25];
    float* n0 = &s_hn[threadIdx.x * 25];
    float* n1 = &s_hn[(BLK + threadIdx.x) * 25];
    #pragma unroll
    for (int j = 0; j < HH; j++) { h0[j] = 0.f; h1[j] = 0.f; c0[j] = 0.f; c1[j] = 0.f; }

    const float* xb0 = x + (size_t)b0 * (TT * FF);
    const float* xb1 = x + (size_t)b1 * (TT * FF);
    const int t0 = dir ? (TT - 1) : 0;
    const int dt = dir ? -1 : 1;

    const ulonglong2* __restrict__ wdir = c_pk.w[dir];
    const u64* __restrict__ bifd = c_pk.bif[dir];
    const u64* __restrict__ bgod = c_pk.bgo[dir];

    for (int s = 0; s < NSTEPS; ++s) {
        const int toff = (t0 + dt * s) * FF;
        float xv0[FF], xv1[FF];
        #pragma unroll
        for (int k = 0; k < FF / 2; ++k) {
            float2 v0 = __ldg((const float2*)(xb0 + toff) + k);
            float2 v1 = __ldg((const float2*)(xb1 + toff) + k);
            xv0[2 * k] = v0.x; xv0[2 * k + 1] = v0.y;
            xv1[2 * k] = v1.x; xv1[2 * k + 1] = v1.y;
        }

        #pragma unroll 1
        for (int j = 0; j < HH; ++j) {
            u64 aif0 = bifd[j], ago0 = bgod[j];
            u64 aif1 = aif0,    ago1 = ago0;
            const ulonglong2* wp = &wdir[j * KK];
            #pragma unroll
            for (int k = 0; k < FF; ++k) {
                ulonglong2 w = wp[k];                 // uniform constant load (LDCU path)
                u64 v0 = dup2(xv0[k]);
                u64 v1 = dup2(xv1[k]);
                ffma2(aif0, v0, w.x); ffma2(ago0, v0, w.y);
                ffma2(aif1, v1, w.x); ffma2(ago1, v1, w.y);
            }
            #pragma unroll
            for (int k = 0; k < HH; ++k) {
                ulonglong2 w = wp[FF + k];
                u64 v0 = dup2(h0[k]);
                u64 v1 = dup2(h1[k]);
                ffma2(aif0, v0, w.x); ffma2(ago0, v0, w.y);
                ffma2(aif1, v1, w.x); ffma2(ago1, v1, w.y);
            }
            {
                float ai, af, ag, ao;
                unpack2(aif0, ai, af); unpack2(ago0, ag, ao);
                float ii = sigf_(ai), ff = sigf_(af), oo = sigf_(ao), gg = tanhf_(ag);
                float cn = ff * c0[j] + ii * gg;
                c0[j] = cn; n0[j] = oo * tanhf_(cn);
            }
            {
                float ai, af, ag, ao;
                unpack2(aif1, ai, af); unpack2(ago1, ag, ao);
                float ii = sigf_(ai), ff = sigf_(af), oo = sigf_(ao), gg = tanhf_(ag);
                float cn = ff * c1[j] + ii * gg;
                c1[j] = cn; n1[j] = oo * tanhf_(cn);
            }
        }
        #pragma unroll
        for (int j = 0; j < HH; ++j) { h0[j] = n0[j]; h1[j] = n1[j]; }  // private rows
    }

    // Fused head: partial logits for this direction, accumulated atomically.
    const float* hw = c_pk.hw[dir];
    float p00 = 0.f, p01 = 0.f, p02 = 0.f, p03 = 0.f;
    float p10 = 0.f, p11 = 0.f, p12 = 0.f, p13 = 0.f;
    #pragma unroll
    for (int j = 0; j < HH; ++j) {
        float w0 = hw[j], w1 = hw[HH + j], w2 = hw[2 * HH + j], w3 = hw[3 * HH + j];
        p00 += h0[j] * w0; p01 += h0[j] * w1; p02 += h0[j] * w2; p03 += h0[j] * w3;
        p10 += h1[j] * w0; p11 += h1[j] * w1; p12 += h1[j] * w2; p13 += h1[j] * w3;
    }
    float* ob0 = out + (size_t)b0 * NCLS;
    atomicAdd(ob0 + 0, p00); atomicAdd(ob0 + 1, p01);
    atomicAdd(ob0 + 2, p02); atomicAdd(ob0 + 3, p03);
    float* ob1 = out + (size_t)b1 * NCLS;
    atomicAdd(ob1 + 0, p10); atomicAdd(ob1 + 1, p11);
    atomicAdd(ob1 + 2, p12); atomicAdd(ob1 + 3, p13);
}

extern "C" void kernel_launch(void* const* d_in, const int* in_sizes, int n_in,
                              void* d_out, int out_size)
{
    const float* x      = (const float*)d_in[0];
    const float* wih_f  = (const float*)d_in[1];
    const float* whh_f  = (const float*)d_in[2];
    const float* bih_f  = (const float*)d_in[3];
    const float* bhh_f  = (const float*)d_in[4];
    const float* wih_b  = (const float*)d_in[5];
    const float* whh_b  = (const float*)d_in[6];
    const float* bih_b  = (const float*)d_in[7];
    const float* bhh_b  = (const float*)d_in[8];
    const float* head_w = (const float*)d_in[9];
    const float* head_b = (const float*)d_in[10];
    float* out = (float*)d_out;

    // 1) pack params into device scratch
    prep_pack_kernel<<<1, 256>>>(wih_f, whh_f, bih_f, bhh_f,
                                 wih_b, whh_b, bih_b, bhh_b, head_w);
    // 2) device->constant copy (graph-capturable memcpy node, no alloc)
    void* src = nullptr;
    cudaGetSymbolAddress(&src, g_pk);
    cudaMemcpyToSymbolAsync(c_pk, src, sizeof(CPack), 0, cudaMemcpyDeviceToDevice, 0);
    // 3) bias-init output, 4) main kernel (single balanced wave: 1024 CTAs, 7/SM)
    init_out_kernel<<<BTOT / 256, 256>>>(head_b, out);
    lstm_kernel<<<(BTOT / (2 * BLK)) * 2, BLK>>>(x, out);
}

// round 8
// speedup vs baseline: 1.0199x; 1.0199x over previous
#include <cuda_runtime.h>
#include <cstdint>

// Problem constants
#define TT     25
#define FF     14
#define HH     24
#define KK     38     // FF + HH fused weight row
#define NSTEPS 13     // fwd needs t=0..12, bwd needs t=24..12
#define BTOT   65536
#define BLK    64
#define NCLS   4

typedef unsigned long long u64;

// ---- packed f32x2 helpers (Blackwell) ----
__device__ __forceinline__ u64 pack2(float lo, float hi) {
    u64 r; asm("mov.b64 %0, {%1, %2};" : "=l"(r) : "f"(lo), "f"(hi)); return r;
}
__device__ __forceinline__ u64 dup2(float v) {
    u64 r; asm("mov.b64 %0, {%1, %1};" : "=l"(r) : "f"(v)); return r;
}
__device__ __forceinline__ void unpack2(u64 v, float& lo, float& hi) {
    asm("mov.b64 {%0, %1}, %2;" : "=f"(lo), "=f"(hi) : "l"(v));
}
__device__ __forceinline__ void ffma2(u64& d, u64 a, u64 b) {
    asm("fma.rn.f32x2 %0, %1, %2, %0;" : "+l"(d) : "l"(a), "l"(b));
}

// ---- fast, accurate activations ----
__device__ __forceinline__ float ex2f_(float x) {
    float y; asm("ex2.approx.f32 %0, %1;" : "=f"(y) : "f"(x)); return y;
}
__device__ __forceinline__ float rcpf_(float x) {
    float y; asm("rcp.approx.f32 %0, %1;" : "=f"(y) : "f"(x)); return y;
}
__device__ __forceinline__ float sigf_(float x) {
    return rcpf_(1.0f + ex2f_(-1.4426950408889634f * x));
}
__device__ __forceinline__ float tanhf_(float x) {
    x = fminf(fmaxf(x, -30.0f), 30.0f);
    float a = ex2f_(2.8853900817779268f * x);
    return (a - 1.0f) * rcpf_(a + 1.0f);
}

// ---- packed parameter blob in GLOBAL memory (read via broadcast __ldg) ----
struct WPack {
    ulonglong2 w[2][HH * KK];   // [dir][j*KK+k] = {(wi,wf),(wg,wo)}  29184 B
    u64 bif[2][HH];             // fused biases, gate-paired            384 B
    u64 bgo[2][HH];             //                                      384 B
    float hw[2][NCLS * HH];     // head_w slice per direction           768 B
};
__device__ WPack g_pk;

__global__ __launch_bounds__(256)
void prep_pack_kernel(const float* __restrict__ wih_f, const float* __restrict__ whh_f,
                      const float* __restrict__ bih_f, const float* __restrict__ bhh_f,
                      const float* __restrict__ wih_b, const float* __restrict__ whh_b,
                      const float* __restrict__ bih_b, const float* __restrict__ bhh_b,
                      const float* __restrict__ head_w)
{
    for (int d = 0; d < 2; ++d) {
        const float* wih = d ? wih_b : wih_f;
        const float* whh = d ? whh_b : whh_f;
        const float* bih = d ? bih_b : bih_f;
        const float* bhh = d ? bhh_b : bhh_f;
        for (int i = threadIdx.x; i < HH * KK; i += 256) {
            int j = i / KK, k = i % KK;
            float wi, wf, wg, wo;
            if (k < FF) {
                wi = wih[j * FF + k];
                wf = wih[(j + HH) * FF + k];
                wg = wih[(j + 2 * HH) * FF + k];
                wo = wih[(j + 3 * HH) * FF + k];
            } else {
                int kk = k - FF;
                wi = whh[j * HH + kk];
                wf = whh[(j + HH) * HH + kk];
                wg = whh[(j + 2 * HH) * HH + kk];
                wo = whh[(j + 3 * HH) * HH + kk];
            }
            ulonglong2 w; w.x = pack2(wi, wf); w.y = pack2(wg, wo);
            g_pk.w[d][i] = w;
        }
        if (threadIdx.x < HH) {
            int j = threadIdx.x;
            g_pk.bif[d][j] = pack2(bih[j] + bhh[j],                   bih[j + HH] + bhh[j + HH]);
            g_pk.bgo[d][j] = pack2(bih[j + 2 * HH] + bhh[j + 2 * HH], bih[j + 3 * HH] + bhh[j + 3 * HH]);
        }
        if (threadIdx.x < NCLS * HH) {
            int m = threadIdx.x / HH, j = threadIdx.x % HH;
            g_pk.hw[d][m * HH + j] = head_w[m * (2 * HH) + d * HH + j];
        }
    }
}

__global__ __launch_bounds__(256)
void init_out_kernel(const float* __restrict__ head_b, float* __restrict__ out)
{
    const int b = blockIdx.x * blockDim.x + threadIdx.x;
    ((float4*)out)[b] = make_float4(head_b[0], head_b[1], head_b[2], head_b[3]);
}

__global__ __launch_bounds__(BLK, 7)
void lstm_kernel(const float* __restrict__ x, float* __restrict__ out)
{
    // Only per-thread state in smem; weights stream from L1-resident global.
    __shared__ float s_c [2 * BLK * 25];    // 12800 B  (stride 25: conflict-free)
    __shared__ float s_hn[2 * BLK * 25];    // 12800 B

    const int dir = blockIdx.x & 1;

    // Two batch elements per thread
    const int b0 = (blockIdx.x >> 1) * (2 * BLK) + threadIdx.x;
    const int b1 = b0 + BLK;

    float h0[HH], h1[HH];
    float* c0 = &s_c [threadIdx.x * 25];
    float* c1 = &s_c [(BLK + threadIdx.x) * 25];
    float* n0 = &s_hn[threadIdx.x * 25];
    float* n1 = &s_hn[(BLK + threadIdx.x) * 25];
    #pragma unroll
    for (int j = 0; j < HH; j++) { h0[j] = 0.f; h1[j] = 0.f; c0[j] = 0.f; c1[j] = 0.f; }

    const float* xb0 = x + (size_t)b0 * (TT * FF);
    const float* xb1 = x + (size_t)b1 * (TT * FF);
    const int t0 = dir ? (TT - 1) : 0;
    const int dt = dir ? -1 : 1;

    const ulonglong2* __restrict__ wdir = g_pk.w[dir];
    const u64* __restrict__ bifd = g_pk.bif[dir];
    const u64* __restrict__ bgod = g_pk.bgo[dir];

    for (int s = 0; s < NSTEPS; ++s) {
        const int toff = (t0 + dt * s) * FF;
        float xv0[FF], xv1[FF];
        #pragma unroll
        for (int k = 0; k < FF / 2; ++k) {
            float2 v0 = __ldg((const float2*)(xb0 + toff) + k);
            float2 v1 = __ldg((const float2*)(xb1 + toff) + k);
            xv0[2 * k] = v0.x; xv0[2 * k + 1] = v0.y;
            xv1[2 * k] = v1.x; xv1[2 * k + 1] = v1.y;
        }

        #pragma unroll 1
        for (int j = 0; j < HH; ++j) {
            u64 aif0 = __ldg(&bifd[j]), ago0 = __ldg(&bgod[j]);
            u64 aif1 = aif0,            ago1 = ago0;
            const ulonglong2* wp = &wdir[j * KK];
            #pragma unroll
            for (int k = 0; k < FF; ++k) {
                ulonglong2 w = __ldg(wp + k);         // broadcast LDG.128, L1-resident
                u64 v0 = dup2(xv0[k]);
                u64 v1 = dup2(xv1[k]);
                ffma2(aif0, v0, w.x); ffma2(ago0, v0, w.y);
                ffma2(aif1, v1, w.x); ffma2(ago1, v1, w.y);
            }
            #pragma unroll
            for (int k = 0; k < HH; ++k) {
                ulonglong2 w = __ldg(wp + FF + k);
                u64 v0 = dup2(h0[k]);
                u64 v1 = dup2(h1[k]);
                ffma2(aif0, v0, w.x); ffma2(ago0, v0, w.y);
                ffma2(aif1, v1, w.x); ffma2(ago1, v1, w.y);
            }
            {
                float ai, af, ag, ao;
                unpack2(aif0, ai, af); unpack2(ago0, ag, ao);
                float ii = sigf_(ai), ff = sigf_(af), oo = sigf_(ao), gg = tanhf_(ag);
                float cn = ff * c0[j] + ii * gg;
                c0[j] = cn; n0[j] = oo * tanhf_(cn);
            }
            {
                float ai, af, ag, ao;
                unpack2(aif1, ai, af); unpack2(ago1, ag, ao);
                float ii = sigf_(ai), ff = sigf_(af), oo = sigf_(ao), gg = tanhf_(ag);
                float cn = ff * c1[j] + ii * gg;
                c1[j] = cn; n1[j] = oo * tanhf_(cn);
            }
        }
        #pragma unroll
        for (int j = 0; j < HH; ++j) { h0[j] = n0[j]; h1[j] = n1[j]; }  // private rows
    }

    // Fused head: partial logits for this direction, accumulated atomically.
    const float* hw = g_pk.hw[dir];
    float p00 = 0.f, p01 = 0.f, p02 = 0.f, p03 = 0.f;
    float p10 = 0.f, p11 = 0.f, p12 = 0.f, p13 = 0.f;
    #pragma unroll
    for (int j = 0; j < HH; ++j) {
        float w0 = __ldg(hw + j), w1 = __ldg(hw + HH + j);
        float w2 = __ldg(hw + 2 * HH + j), w3 = __ldg(hw + 3 * HH + j);
        p00 += h0[j] * w0; p01 += h0[j] * w1; p02 += h0[j] * w2; p03 += h0[j] * w3;
        p10 += h1[j] * w0; p11 += h1[j] * w1; p12 += h1[j] * w2; p13 += h1[j] * w3;
    }
    float* ob0 = out + (size_t)b0 * NCLS;
    atomicAdd(ob0 + 0, p00); atomicAdd(ob0 + 1, p01);
    atomicAdd(ob0 + 2, p02); atomicAdd(ob0 + 3, p03);
    float* ob1 = out + (size_t)b1 * NCLS;
    atomicAdd(ob1 + 0, p10); atomicAdd(ob1 + 1, p11);
    atomicAdd(ob1 + 2, p12); atomicAdd(ob1 + 3, p13);
}

extern "C" void kernel_launch(void* const* d_in, const int* in_sizes, int n_in,
                              void* d_out, int out_size)
{
    const float* x      = (const float*)d_in[0];
    const float* wih_f  = (const float*)d_in[1];
    const float* whh_f  = (const float*)d_in[2];
    const float* bih_f  = (const float*)d_in[3];
    const float* bhh_f  = (const float*)d_in[4];
    const float* wih_b  = (const float*)d_in[5];
    const float* whh_b  = (const float*)d_in[6];
    const float* bih_b  = (const float*)d_in[7];
    const float* bhh_b  = (const float*)d_in[8];
    const float* head_w = (const float*)d_in[9];
    const float* head_b = (const float*)d_in[10];
    float* out = (float*)d_out;

    prep_pack_kernel<<<1, 256>>>(wih_f, whh_f, bih_f, bhh_f,
                                 wih_b, whh_b, bih_b, bhh_b, head_w);
    init_out_kernel<<<BTOT / 256, 256>>>(head_b, out);
    // 1024 CTAs, 7/SM -> single balanced wave, 14 warps/SM
    lstm_kernel<<<(BTOT / (2 * BLK)) * 2, BLK>>>(x, out);
}

// round 9
// speedup vs baseline: 1.4939x; 1.4648x over previous
#include <cuda_runtime.h>

// Problem constants
#define TT     25
#define FF     14
#define HH     24
#define KK     38     // FF + HH fused weight row
#define NSTEPS 13     // WINDOW_HALF + 1 : fwd needs t=0..12, bwd needs t=24..12
#define BTOT   65536
#define BLK    64
#define NCLS   4

typedef unsigned long long u64;

// ---- packed f32x2 helpers (Blackwell) ----
__device__ __forceinline__ u64 pack2(float lo, float hi) {
    u64 r; asm("mov.b64 %0, {%1, %2};" : "=l"(r) : "f"(lo), "f"(hi)); return r;
}
__device__ __forceinline__ u64 dup2(float v) {
    u64 r; asm("mov.b64 %0, {%1, %1};" : "=l"(r) : "f"(v)); return r;
}
__device__ __forceinline__ void unpack2(u64 v, float& lo, float& hi) {
    asm("mov.b64 {%0, %1}, %2;" : "=f"(lo), "=f"(hi) : "l"(v));
}
__device__ __forceinline__ void ffma2(u64& d, u64 a, u64 b) {
    asm("fma.rn.f32x2 %0, %1, %2, %0;" : "+l"(d) : "l"(a), "l"(b));
}

// ---- fast, accurate activations (EX2/RCP: ~2 ulp, far inside 1e-3 budget) ----
__device__ __forceinline__ float ex2f_(float x) {
    float y; asm("ex2.approx.f32 %0, %1;" : "=f"(y) : "f"(x)); return y;
}
__device__ __forceinline__ float rcpf_(float x) {
    float y; asm("rcp.approx.f32 %0, %1;" : "=f"(y) : "f"(x)); return y;
}
__device__ __forceinline__ float sigf_(float x) {
    return rcpf_(1.0f + ex2f_(-1.4426950408889634f * x));
}
__device__ __forceinline__ float tanhf_(float x) {
    x = fminf(fmaxf(x, -30.0f), 30.0f);
    float a = ex2f_(2.8853900817779268f * x);
    return (a - 1.0f) * rcpf_(a + 1.0f);
}

__global__ __launch_bounds__(256)
void init_out_kernel(const float* __restrict__ head_b, float* __restrict__ out)
{
    const int b = blockIdx.x * blockDim.x + threadIdx.x;
    ((float4*)out)[b] = make_float4(head_b[0], head_b[1], head_b[2], head_b[3]);
}

__global__ __launch_bounds__(BLK, 7)
void lstm_kernel(const float* __restrict__ x,
                 const float* __restrict__ wih_f, const float* __restrict__ whh_f,
                 const float* __restrict__ bih_f, const float* __restrict__ bhh_f,
                 const float* __restrict__ wih_b, const float* __restrict__ whh_b,
                 const float* __restrict__ bih_b, const float* __restrict__ bhh_b,
                 const float* __restrict__ head_w, float* __restrict__ out)
{
    // Weights in smem (broadcast LDS.128 path); c-state in LOCAL memory
    // (coalesced per-lane, frees 12.8KB smem -> 7 CTAs/SM).
    __shared__ ulonglong2 s_w[HH * KK];     // 14592 B
    __shared__ u64 s_bif[HH];               //   192 B
    __shared__ u64 s_bgo[HH];               //   192 B
    __shared__ float s_hn[2 * BLK * 25];    // 12800 B  (new-h staging)
    __shared__ float s_hw[NCLS * HH];       //   384 B

    const int dir = blockIdx.x & 1;
    const float* wih = dir ? wih_b : wih_f;
    const float* whh = dir ? whh_b : whh_f;
    const float* bih = dir ? bih_b : bih_f;
    const float* bhh = dir ? bhh_b : bhh_f;

    for (int i = threadIdx.x; i < HH * KK; i += BLK) {
        int j = i / KK, k = i % KK;
        float wi, wf, wg, wo;
        if (k < FF) {
            wi = wih[j * FF + k];
            wf = wih[(j + HH) * FF + k];
            wg = wih[(j + 2 * HH) * FF + k];
            wo = wih[(j + 3 * HH) * FF + k];
        } else {
            int kk = k - FF;
            wi = whh[j * HH + kk];
            wf = whh[(j + HH) * HH + kk];
            wg = whh[(j + 2 * HH) * HH + kk];
            wo = whh[(j + 3 * HH) * HH + kk];
        }
        ulonglong2 w; w.x = pack2(wi, wf); w.y = pack2(wg, wo);
        s_w[i] = w;
    }
    if (threadIdx.x < HH) {
        int j = threadIdx.x;
        s_bif[j] = pack2(bih[j] + bhh[j],                   bih[j + HH] + bhh[j + HH]);
        s_bgo[j] = pack2(bih[j + 2 * HH] + bhh[j + 2 * HH], bih[j + 3 * HH] + bhh[j + 3 * HH]);
    }
    for (int i = threadIdx.x; i < NCLS * HH; i += BLK) {
        int m = i / HH, j = i % HH;
        s_hw[m * HH + j] = head_w[m * (2 * HH) + dir * HH + j];
    }
    __syncthreads();

    // Two batch elements per thread
    const int b0 = (blockIdx.x >> 1) * (2 * BLK) + threadIdx.x;
    const int b1 = b0 + BLK;

    float h0[HH], h1[HH];
    float c0[HH], c1[HH];                    // dynamic-j indexed -> local memory
    float* n0 = &s_hn[threadIdx.x * 25];
    float* n1 = &s_hn[(BLK + threadIdx.x) * 25];
    #pragma unroll
    for (int j = 0; j < HH; j++) { h0[j] = 0.f; h1[j] = 0.f; c0[j] = 0.f; c1[j] = 0.f; }

    const float* xb0 = x + (size_t)b0 * (TT * FF);
    const float* xb1 = x + (size_t)b1 * (TT * FF);
    const int t0 = dir ? (TT - 1) : 0;
    const int dt = dir ? -1 : 1;

    for (int s = 0; s < NSTEPS; ++s) {
        const int toff = (t0 + dt * s) * FF;
        float xv0[FF], xv1[FF];
        #pragma unroll
        for (int k = 0; k < FF / 2; ++k) {
            float2 v0 = __ldg((const float2*)(xb0 + toff) + k);
            float2 v1 = __ldg((const float2*)(xb1 + toff) + k);
            xv0[2 * k] = v0.x; xv0[2 * k + 1] = v0.y;
            xv1[2 * k] = v1.x; xv1[2 * k + 1] = v1.y;
        }

        #pragma unroll 1
        for (int j = 0; j < HH; ++j) {
            u64 aif0 = s_bif[j], ago0 = s_bgo[j];
            u64 aif1 = aif0,     ago1 = ago0;
            const ulonglong2* wp = &s_w[j * KK];
            #pragma unroll
            for (int k = 0; k < FF; ++k) {
                ulonglong2 w = wp[k];                 // broadcast LDS.128; 4 FFMA2
                u64 v0 = dup2(xv0[k]);
                u64 v1 = dup2(xv1[k]);
                ffma2(aif0, v0, w.x); ffma2(ago0, v0, w.y);
                ffma2(aif1, v1, w.x); ffma2(ago1, v1, w.y);
            }
            #pragma unroll
            for (int k = 0; k < HH; ++k) {
                ulonglong2 w = wp[FF + k];
                u64 v0 = dup2(h0[k]);
                u64 v1 = dup2(h1[k]);
                ffma2(aif0, v0, w.x); ffma2(ago0, v0, w.y);
                ffma2(aif1, v1, w.x); ffma2(ago1, v1, w.y);
            }
            {
                float ai, af, ag, ao;
                unpack2(aif0, ai, af); unpack2(ago0, ag, ao);
                float ii = sigf_(ai), ff = sigf_(af), oo = sigf_(ao), gg = tanhf_(ag);
                float cn = ff * c0[j] + ii * gg;
                c0[j] = cn; n0[j] = oo * tanhf_(cn);
            }
            {
                float ai, af, ag, ao;
                unpack2(aif1, ai, af); unpack2(ago1, ag, ao);
                float ii = sigf_(ai), ff = sigf_(af), oo = sigf_(ao), gg = tanhf_(ag);
                float cn = ff * c1[j] + ii * gg;
                c1[j] = cn; n1[j] = oo * tanhf_(cn);
            }
        }
        #pragma unroll
        for (int j = 0; j < HH; ++j) { h0[j] = n0[j]; h1[j] = n1[j]; }  // private rows
    }

    // Fused head: partial logits for this direction, accumulated atomically.
    float p00 = 0.f, p01 = 0.f, p02 = 0.f, p03 = 0.f;
    float p10 = 0.f, p11 = 0.f, p12 = 0.f, p13 = 0.f;
    #pragma unroll
    for (int j = 0; j < HH; ++j) {
        float w0 = s_hw[j], w1 = s_hw[HH + j], w2 = s_hw[2 * HH + j], w3 = s_hw[3 * HH + j];
        p00 += h0[j] * w0; p01 += h0[j] * w1; p02 += h0[j] * w2; p03 += h0[j] * w3;
        p10 += h1[j] * w0; p11 += h1[j] * w1; p12 += h1[j] * w2; p13 += h1[j] * w3;
    }
    float* ob0 = out + (size_t)b0 * NCLS;
    atomicAdd(ob0 + 0, p00); atomicAdd(ob0 + 1, p01);
    atomicAdd(ob0 + 2, p02); atomicAdd(ob0 + 3, p03);
    float* ob1 = out + (size_t)b1 * NCLS;
    atomicAdd(ob1 + 0, p10); atomicAdd(ob1 + 1, p11);
    atomicAdd(ob1 + 2, p12); atomicAdd(ob1 + 3, p13);
}

extern "C" void kernel_launch(void* const* d_in, const int* in_sizes, int n_in,
                              void* d_out, int out_size)
{
    const float* x      = (const float*)d_in[0];
    const float* wih_f  = (const float*)d_in[1];
    const float* whh_f  = (const float*)d_in[2];
    const float* bih_f  = (const float*)d_in[3];
    const float* bhh_f  = (const float*)d_in[4];
    const float* wih_b  = (const float*)d_in[5];
    const float* whh_b  = (const float*)d_in[6];
    const float* bih_b  = (const float*)d_in[7];
    const float* bhh_b  = (const float*)d_in[8];
    const float* head_w = (const float*)d_in[9];
    const float* head_b = (const float*)d_in[10];
    float* out = (float*)d_out;

    init_out_kernel<<<BTOT / 256, 256>>>(head_b, out);
    // 1024 CTAs @ 7/SM -> single balanced wave, 14 warps/SM
    lstm_kernel<<<(BTOT / (2 * BLK)) * 2, BLK>>>(x, wih_f, whh_f, bih_f, bhh_f,
                                                 wih_b, whh_b, bih_b, bhh_b,
                                                 head_w, out);
}